// round 14
// baseline (speedup 1.0000x reference)
#include <cuda_runtime.h>
#include <cuda_bf16.h>
#include <cstdint>
#include <math.h>

#define NN 10000
#define NPAD 10112          // 79 * 128
#define EE 320000
#define DIN 256
#define HEADS 8
#define DH 32
#define HD 256
#define NTOT 1024           // 4 weights x 256 output cols
#define CHUNK0_NODES 5120   // 40 gemm row-blocks
#define CHUNK0_BLKS 40
#define CHUNK1_BLKS 39      // covers rows 5120..10111 (padded)

// ---------------- scratch (static device globals; no allocation) ----------------
// double-buffered Q/K/V/XR (ping-pong across layers for attn->gemm pipelining)
__device__ float g_Qb[2][NN * HD];
__device__ float g_Kb[2][NN * HD];
__device__ float g_Vb[2][NN * HD];
__device__ float g_XRb[2][NN * HD];
__device__ int   g_rowptr[NN + 1];
__device__ int   g_cnt[NN];
__device__ int   g_srcs[EE];
__device__ float g_ews[EE];
// split-bf16 operands for tensor-core GEMM (double-buffered weights)
__device__ __nv_bfloat16 g_Xhi[NPAD * DIN];
__device__ __nv_bfloat16 g_Xlo[NPAD * DIN];
__device__ __nv_bfloat16 g_Wthi0[NTOT * DIN];
__device__ __nv_bfloat16 g_Wtlo0[NTOT * DIN];
__device__ float g_bcat0[NTOT];
__device__ __nv_bfloat16 g_Wthi1[NTOT * DIN];
__device__ __nv_bfloat16 g_Wtlo1[NTOT * DIN];
__device__ float g_bcat1[NTOT];

__device__ __forceinline__ uint32_t smem_u32(const void* p) {
    uint32_t a;
    asm("{ .reg .u64 t; cvta.to.shared.u64 t, %1; cvt.u32.u64 %0, t; }" : "=r"(a) : "l"(p));
    return a;
}

__device__ __forceinline__ void ldm_x4(uint32_t* r, uint32_t addr) {
    asm volatile("ldmatrix.sync.aligned.m8n8.x4.shared.b16 {%0,%1,%2,%3}, [%4];"
                 : "=r"(r[0]), "=r"(r[1]), "=r"(r[2]), "=r"(r[3]) : "r"(addr));
}

__device__ __forceinline__ void mma16816(float* c, const uint32_t* a, const uint32_t* b) {
    asm volatile(
        "mma.sync.aligned.m16n8k16.row.col.f32.bf16.bf16.f32 "
        "{%0,%1,%2,%3}, {%4,%5,%6,%7}, {%8,%9}, {%0,%1,%2,%3};"
        : "+f"(c[0]), "+f"(c[1]), "+f"(c[2]), "+f"(c[3])
        : "r"(a[0]), "r"(a[1]), "r"(a[2]), "r"(a[3]), "r"(b[0]), "r"(b[1]));
}

__device__ __forceinline__ void cp16(uint32_t dst, const void* src) {
    asm volatile("cp.async.cg.shared.global [%0], [%1], 16;" :: "r"(dst), "l"(src));
}
#define CP_COMMIT() asm volatile("cp.async.commit_group;" ::: "memory")
#define CP_WAIT(n)  asm volatile("cp.async.wait_group %0;" :: "n"(n) : "memory")

// ---------------- CSR build ----------------
__global__ void zero_cnt_kernel() {
    int i = blockIdx.x * blockDim.x + threadIdx.x;
    if (i < NN) g_cnt[i] = 0;
}

__global__ void count_deg_kernel(const int* __restrict__ ei, int E) {
    int base = (blockIdx.x * blockDim.x + threadIdx.x) * 4;
#pragma unroll
    for (int i = 0; i < 4; i++) {
        int e = base + i;
        if (e < E) {
            int d = ei[E + e];
            if (d >= 0 && d < NN) atomicAdd(&g_cnt[d], 1);
        }
    }
}

__global__ void scan_deg_kernel(int E) {
    __shared__ int warp_sums[32];
    const int IT = 10;
    int t = threadIdx.x;
    int lane = t & 31, wid = t >> 5;
    int base = t * IT;
    int loc[IT];
    int tot = 0;
#pragma unroll
    for (int i = 0; i < IT; i++) {
        int idx = base + i;
        int v = (idx < NN) ? g_cnt[idx] : 0;
        if (idx < NN) g_cnt[idx] = 0;
        loc[i] = v;
        tot += v;
    }
    int incl = tot;
#pragma unroll
    for (int o = 1; o < 32; o <<= 1) {
        int n = __shfl_up_sync(0xffffffffu, incl, o);
        if (lane >= o) incl += n;
    }
    if (lane == 31) warp_sums[wid] = incl;
    __syncthreads();
    if (wid == 0) {
        int v = warp_sums[lane];
        __syncwarp();
#pragma unroll
        for (int o = 1; o < 32; o <<= 1) {
            int n = __shfl_up_sync(0xffffffffu, v, o);
            if (lane >= o) v += n;
        }
        warp_sums[lane] = v;
    }
    __syncthreads();
    int run = (incl - tot) + (wid > 0 ? warp_sums[wid - 1] : 0);
#pragma unroll
    for (int i = 0; i < IT; i++) {
        int idx = base + i;
        if (idx < NN) g_rowptr[idx] = run;
        run += loc[i];
    }
    if (t == 0) g_rowptr[NN] = E;
}

__global__ void fill_csr_kernel(const int* __restrict__ ei,
                                const float* __restrict__ ew, int E) {
    int base = (blockIdx.x * blockDim.x + threadIdx.x) * 4;
#pragma unroll
    for (int i = 0; i < 4; i++) {
        int e = base + i;
        if (e < E) {
            int d = ei[E + e];
            int s = ei[e];
            if (d >= 0 && d < NN && s >= 0 && s < NN) {
                int pos = atomicAdd(&g_cnt[d], 1);
                int o = g_rowptr[d] + pos;
                if (o >= 0 && o < E) {
                    g_srcs[o] = s;
                    g_ews[o]  = ew[e];
                }
            }
        }
    }
}

// ---------------- conversions: fp32 -> split bf16 ----------------
__global__ __launch_bounds__(1024) void conv_x_kernel(const float* __restrict__ X) {
    int idx = blockIdx.x * blockDim.x + threadIdx.x;
    int row = idx >> 8;
    float v = (row < NN) ? X[idx] : 0.0f;
    __nv_bfloat16 h = __float2bfloat16(v);
    float hv = __bfloat162float(h);
    g_Xhi[idx] = h;
    g_Xlo[idx] = __float2bfloat16(v - hv);
}

__global__ __launch_bounds__(256) void conv_w_kernel(
    const float* __restrict__ W0, const float* __restrict__ W1,
    const float* __restrict__ W2, const float* __restrict__ W3,
    const float* __restrict__ b0, const float* __restrict__ b1,
    const float* __restrict__ b2, const float* __restrict__ b3,
    int dstbuf)
{
    int b = blockIdx.x;
    int w = b >> 8;
    int n = b & 255;
    const float* W; const float* bias;
    switch (w) {
        case 0: W = W0; bias = b0; break;
        case 1: W = W1; bias = b1; break;
        case 2: W = W2; bias = b2; break;
        default: W = W3; bias = b3; break;
    }
    __nv_bfloat16* Whi = dstbuf ? g_Wthi1 : g_Wthi0;
    __nv_bfloat16* Wlo = dstbuf ? g_Wtlo1 : g_Wtlo0;
    float* bc = dstbuf ? g_bcat1 : g_bcat0;
    int k = threadIdx.x;
    float v = W[k * 256 + n];
    __nv_bfloat16 h = __float2bfloat16(v);
    float hv = __bfloat162float(h);
    Whi[b * 256 + k] = h;
    Wlo[b * 256 + k] = __float2bfloat16(v - hv);
    if (k == 0) bc[b] = bias[n];
}

// ---------------- pipelined mma GEMM: rows [mblk0*128, ...) x [256,1024] ----------------
#define KSTR 40
#define STG_ELEMS 20480
#define OFF_AH 0
#define OFF_AL 5120
#define OFF_BH 10240
#define OFF_BL 15360
#define NSTAGE 2
#define GEMM_SMEM (NSTAGE * STG_ELEMS * 2)   // 81920 bytes

__device__ __forceinline__ void gemm_stage(
    __nv_bfloat16* sb, int m0, int n0, int k0, int tid,
    const __nv_bfloat16* __restrict__ Whi, const __nv_bfloat16* __restrict__ Wlo)
{
#pragma unroll
    for (int i = 0; i < 8; i++) {
        int u = tid + i * 256;            // 0..2047, 16B units
        const __nv_bfloat16* src;
        uint32_t doff;
        if (u < 512) {
            int r = u >> 2, c = u & 3;
            src = &g_Xhi[(m0 + r) * 256 + k0 + c * 8];
            doff = OFF_AH + (uint32_t)(r * KSTR + c * 8);
        } else if (u < 1024) {
            int v = u - 512;
            int r = v >> 2, c = v & 3;
            src = &g_Xlo[(m0 + r) * 256 + k0 + c * 8];
            doff = OFF_AL + (uint32_t)(r * KSTR + c * 8);
        } else if (u < 1536) {
            int v = u - 1024;
            int r = v >> 2, c = v & 3;
            src = &Whi[(n0 + r) * 256 + k0 + c * 8];
            doff = OFF_BH + (uint32_t)(r * KSTR + c * 8);
        } else {
            int v = u - 1536;
            int r = v >> 2, c = v & 3;
            src = &Wlo[(n0 + r) * 256 + k0 + c * 8];
            doff = OFF_BL + (uint32_t)(r * KSTR + c * 8);
        }
        cp16(smem_u32(sb + doff), src);
    }
}

__global__ __launch_bounds__(256, 2) void gemm_mma_kernel(int wbuf, int qsel, int mblk0)
{
    extern __shared__ __nv_bfloat16 dsm[];
    const __nv_bfloat16* Whi = wbuf ? g_Wthi1 : g_Wthi0;
    const __nv_bfloat16* Wlo = wbuf ? g_Wtlo1 : g_Wtlo0;
    const float* bcat = wbuf ? g_bcat1 : g_bcat0;

    int tid = threadIdx.x;
    int lane = tid & 31;
    int warp = tid >> 5;
    int warpM = warp & 3;        // 0..3 (32 rows each)
    int warpN = warp >> 2;       // 0..1 (64 cols each)
    int m0 = (blockIdx.x + mblk0) * 128;
    int n0 = blockIdx.y * 128;

    float acc[2][8][4] = {};

    int a_j = lane & 7;
    int a_rowoff = ((lane >> 3) & 1) * 8;
    int a_coloff = (lane >> 4) * 8;
    int b_j = lane & 7;
    int b_rowoff = (lane >> 4) * 8;
    int b_coloff = ((lane >> 3) & 1) * 8;

    gemm_stage(dsm, m0, n0, 0, tid, Whi, Wlo);
    CP_COMMIT();

    for (int kc = 0; kc < 8; kc++) {
        __nv_bfloat16* cur = dsm + (kc & 1) * STG_ELEMS;
        if (kc < 7) {
            gemm_stage(dsm + ((kc + 1) & 1) * STG_ELEMS, m0, n0, (kc + 1) * 32, tid, Whi, Wlo);
            CP_COMMIT();
            CP_WAIT(1);
        } else {
            CP_WAIT(0);
        }
        __syncthreads();

        uint32_t ah_b = smem_u32(cur + OFF_AH);
        uint32_t al_b = smem_u32(cur + OFF_AL);
        uint32_t bh_b = smem_u32(cur + OFF_BH);
        uint32_t bl_b = smem_u32(cur + OFF_BL);

#pragma unroll
        for (int ks = 0; ks < 2; ks++) {
            int kk = ks * 16;
            uint32_t ah[2][4], al[2][4];
#pragma unroll
            for (int mi = 0; mi < 2; mi++) {
                int rbase = warpM * 32 + mi * 16;
                uint32_t off = (uint32_t)((rbase + a_rowoff + a_j) * KSTR + kk + a_coloff) * 2;
                ldm_x4(ah[mi], ah_b + off);
                ldm_x4(al[mi], al_b + off);
            }
#pragma unroll
            for (int half = 0; half < 2; half++) {
                uint32_t bh[4][2], bl[4][2];
#pragma unroll
                for (int bi = 0; bi < 2; bi++) {
                    int nb = warpN * 64 + half * 32 + bi * 16;
                    uint32_t off = (uint32_t)((nb + b_rowoff + b_j) * KSTR + kk + b_coloff) * 2;
                    uint32_t th[4], tl[4];
                    ldm_x4(th, bh_b + off);
                    ldm_x4(tl, bl_b + off);
                    bh[bi * 2][0] = th[0]; bh[bi * 2][1] = th[1];
                    bh[bi * 2 + 1][0] = th[2]; bh[bi * 2 + 1][1] = th[3];
                    bl[bi * 2][0] = tl[0]; bl[bi * 2][1] = tl[1];
                    bl[bi * 2 + 1][0] = tl[2]; bl[bi * 2 + 1][1] = tl[3];
                }
#pragma unroll
                for (int mi = 0; mi < 2; mi++)
#pragma unroll
                    for (int ni = 0; ni < 4; ni++) {
                        float* a4 = acc[mi][half * 4 + ni];
                        mma16816(a4, ah[mi], bh[ni]);
                        mma16816(a4, ah[mi], bl[ni]);
                        mma16816(a4, al[mi], bh[ni]);
                    }
            }
        }
        __syncthreads();
    }

    int wsel = n0 >> 8;
    float* C = (wsel == 0) ? g_Qb[qsel] : (wsel == 1) ? g_Kb[qsel]
             : (wsel == 2) ? g_Vb[qsel] : g_XRb[qsel];
    int cbase = n0 & 255;
#pragma unroll
    for (int mi = 0; mi < 2; mi++) {
        int m = m0 + warpM * 32 + mi * 16 + (lane >> 2);
#pragma unroll
        for (int nj = 0; nj < 8; nj++) {
            int ncol = warpN * 64 + (nj >> 2) * 32 + (nj & 3) * 8 + (lane & 3) * 2;
            int ng = n0 + ncol;
            int col = cbase + ncol;
            float b0v = bcat[ng], b1v = bcat[ng + 1];
            if (m < NN) {
                float2 o = make_float2(acc[mi][nj][0] + b0v, acc[mi][nj][1] + b1v);
                *(float2*)&C[m * HD + col] = o;
            }
            if (m + 8 < NN) {
                float2 o = make_float2(acc[mi][nj][2] + b0v, acc[mi][nj][3] + b1v);
                *(float2*)&C[(m + 8) * HD + col] = o;
            }
        }
    }
}

// ---------------- fused edge attention + beta epilogue (+ split-bf16 emit) ----------------
// last: 1 if final layer (write Hext), else emit split-bf16 for next GEMM.
__global__ __launch_bounds__(256) void attn_epi_kernel(
    const float* __restrict__ We, const float* __restrict__ Wb,
    int last, float* __restrict__ Hext, int qsel, int node0)
{
    __shared__ float hsum[8];
    int node = blockIdx.x + node0;
    int h = threadIdx.x >> 5;
    int lane = threadIdx.x & 31;
    int g = lane >> 3;
    int j = lane & 7;
    int off = h * DH + j * 4;
    int goff = node * HD + off;
    unsigned gmask = 0xFFu << (g * 8);

    const float* Q = g_Qb[qsel];
    const float* K = g_Kb[qsel];
    const float* V = g_Vb[qsel];
    const float* XR = g_XRb[qsel];

    float4 q4 = *(const float4*)&Q[goff];
    const float sc = 0.17677669529663687f;   // 1/sqrt(32)
    q4.x *= sc; q4.y *= sc; q4.z *= sc; q4.w *= sc;
    float4 we4 = *(const float4*)&We[off];

    float qe = q4.x * we4.x + q4.y * we4.y + q4.z * we4.z + q4.w * we4.w;
    qe += __shfl_xor_sync(gmask, qe, 1);
    qe += __shfl_xor_sync(gmask, qe, 2);
    qe += __shfl_xor_sync(gmask, qe, 4);

    float m = -3.0e38f, s = 0.f, se = 0.f;
    float ax = 0.f, ay = 0.f, az = 0.f, aw = 0.f;
    int beg = g_rowptr[node], end = g_rowptr[node + 1];
    int p = beg + g;
    for (; p + 4 < end; p += 8) {
        int s0 = g_srcs[p];
        int s1 = g_srcs[p + 4];
        float w0 = g_ews[p];
        float w1 = g_ews[p + 4];
        float4 k0 = *(const float4*)&K[s0 * HD + off];
        float4 v0 = *(const float4*)&V[s0 * HD + off];
        float4 k1 = *(const float4*)&K[s1 * HD + off];
        float4 v1 = *(const float4*)&V[s1 * HD + off];
        float d0 = q4.x * k0.x + q4.y * k0.y + q4.z * k0.z + q4.w * k0.w;
        float d1 = q4.x * k1.x + q4.y * k1.y + q4.z * k1.z + q4.w * k1.w;
        d0 += __shfl_xor_sync(gmask, d0, 1);
        d1 += __shfl_xor_sync(gmask, d1, 1);
        d0 += __shfl_xor_sync(gmask, d0, 2);
        d1 += __shfl_xor_sync(gmask, d1, 2);
        d0 += __shfl_xor_sync(gmask, d0, 4);
        d1 += __shfl_xor_sync(gmask, d1, 4);
        float al0 = d0 + w0 * qe;
        float al1 = d1 + w1 * qe;
        float nm = fmaxf(m, fmaxf(al0, al1));
        float corr = __expf(m - nm);
        float p0 = __expf(al0 - nm);
        float p1 = __expf(al1 - nm);
        s = s * corr + p0 + p1;
        se = se * corr + p0 * w0 + p1 * w1;
        ax = ax * corr + p0 * v0.x + p1 * v1.x;
        ay = ay * corr + p0 * v0.y + p1 * v1.y;
        az = az * corr + p0 * v0.z + p1 * v1.z;
        aw = aw * corr + p0 * v0.w + p1 * v1.w;
        m = nm;
    }
    for (; p < end; p += 4) {
        int sN = g_srcs[p];
        float w = g_ews[p];
        float4 k4 = *(const float4*)&K[sN * HD + off];
        float4 v4 = *(const float4*)&V[sN * HD + off];
        float d0 = q4.x * k4.x + q4.y * k4.y + q4.z * k4.z + q4.w * k4.w;
        d0 += __shfl_xor_sync(gmask, d0, 1);
        d0 += __shfl_xor_sync(gmask, d0, 2);
        d0 += __shfl_xor_sync(gmask, d0, 4);
        float alpha = d0 + w * qe;
        float nm = fmaxf(m, alpha);
        float corr = __expf(m - nm);
        float pe = __expf(alpha - nm);
        s = s * corr + pe;
        se = se * corr + pe * w;
        ax = ax * corr + pe * v4.x;
        ay = ay * corr + pe * v4.y;
        az = az * corr + pe * v4.z;
        aw = aw * corr + pe * v4.w;
        m = nm;
    }
#pragma unroll
    for (int o = 8; o <= 16; o <<= 1) {
        float mo = __shfl_xor_sync(0xffffffffu, m, o);
        float so = __shfl_xor_sync(0xffffffffu, s, o);
        float seo = __shfl_xor_sync(0xffffffffu, se, o);
        float bx = __shfl_xor_sync(0xffffffffu, ax, o);
        float by = __shfl_xor_sync(0xffffffffu, ay, o);
        float bz = __shfl_xor_sync(0xffffffffu, az, o);
        float bw = __shfl_xor_sync(0xffffffffu, aw, o);
        float nm = fmaxf(m, mo);
        float c1 = __expf(m - nm);
        float c2 = __expf(mo - nm);
        s = s * c1 + so * c2;
        se = se * c1 + seo * c2;
        ax = ax * c1 + bx * c2;
        ay = ay * c1 + by * c2;
        az = az * c1 + bz * c2;
        aw = aw * c1 + bw * c2;
        m = nm;
    }
    float inv = 1.f / (s + 1e-16f);
    float ox = (ax + se * we4.x) * inv;
    float oy = (ay + se * we4.y) * inv;
    float oz = (az + se * we4.z) * inv;
    float ow = (aw + se * we4.w) * inv;

    float4 xr4 = *(const float4*)&XR[goff];
    float4 wb1 = *(const float4*)&Wb[off];
    float4 wb2 = *(const float4*)&Wb[256 + off];
    float4 wb3 = *(const float4*)&Wb[512 + off];
    float part = ox * (wb1.x + wb3.x) + xr4.x * (wb2.x - wb3.x)
               + oy * (wb1.y + wb3.y) + xr4.y * (wb2.y - wb3.y)
               + oz * (wb1.z + wb3.z) + xr4.z * (wb2.z - wb3.z)
               + ow * (wb1.w + wb3.w) + xr4.w * (wb2.w - wb3.w);
    part += __shfl_xor_sync(0xffffffffu, part, 1);
    part += __shfl_xor_sync(0xffffffffu, part, 2);
    part += __shfl_xor_sync(0xffffffffu, part, 4);
    if (lane == 0) hsum[h] = part;
    __syncthreads();
    float dot = hsum[0] + hsum[1] + hsum[2] + hsum[3] +
                hsum[4] + hsum[5] + hsum[6] + hsum[7];
    float beta = 1.f / (1.f + __expf(-dot));
    float4 hv;
    hv.x = beta * xr4.x + (1.f - beta) * ox;
    hv.y = beta * xr4.y + (1.f - beta) * oy;
    hv.z = beta * xr4.z + (1.f - beta) * oz;
    hv.w = beta * xr4.w + (1.f - beta) * ow;

    if (g == 0) {
        if (last) {
            *(float4*)&Hext[goff] = hv;
        } else {
            __nv_bfloat16 h0 = __float2bfloat16(hv.x);
            __nv_bfloat16 h1 = __float2bfloat16(hv.y);
            __nv_bfloat16 h2 = __float2bfloat16(hv.z);
            __nv_bfloat16 h3 = __float2bfloat16(hv.w);
            __nv_bfloat162 hi01; hi01.x = h0; hi01.y = h1;
            __nv_bfloat162 hi23; hi23.x = h2; hi23.y = h3;
            uint2 hiv = make_uint2(*(uint32_t*)&hi01, *(uint32_t*)&hi23);
            *(uint2*)&g_Xhi[goff] = hiv;
            __nv_bfloat162 lo01, lo23;
            lo01.x = __float2bfloat16(hv.x - __bfloat162float(h0));
            lo01.y = __float2bfloat16(hv.y - __bfloat162float(h1));
            lo23.x = __float2bfloat16(hv.z - __bfloat162float(h2));
            lo23.y = __float2bfloat16(hv.w - __bfloat162float(h3));
            uint2 lov = make_uint2(*(uint32_t*)&lo01, *(uint32_t*)&lo23);
            *(uint2*)&g_Xlo[goff] = lov;
        }
    }
}

// ---------------- host side ----------------
struct LayerParams {
    const float *Wq, *bq, *Wk, *bk, *Wv, *bv, *We, *Wsk, *bsk, *Wb;
};

static cudaStream_t g_sB = nullptr;
static cudaEvent_t g_evFork = nullptr, g_evB = nullptr;
static cudaEvent_t g_evC[4] = {};   // attn chunk events (2 per pipelined layer)
static cudaEvent_t g_evG[2] = {};   // gemm-complete events (layers 2, 3)
namespace {
struct StreamInit {
    StreamInit() {
        cudaStreamCreateWithFlags(&g_sB, cudaStreamNonBlocking);
        cudaEventCreateWithFlags(&g_evFork, cudaEventDisableTiming);
        cudaEventCreateWithFlags(&g_evB, cudaEventDisableTiming);
        for (int i = 0; i < 4; i++) cudaEventCreateWithFlags(&g_evC[i], cudaEventDisableTiming);
        for (int i = 0; i < 2; i++) cudaEventCreateWithFlags(&g_evG[i], cudaEventDisableTiming);
    }
} g_streamInit;
}

extern "C" void kernel_launch(void* const* d_in, const int* in_sizes, int n_in,
                              void* d_out, int out_size)
{
    const float* x  = (const float*)d_in[0];
    const int*   ei = (const int*)d_in[1];
    const float* ew = (const float*)d_in[2];
    int E = in_sizes[2];

    cudaFuncSetAttribute(gemm_mma_kernel,
                         cudaFuncAttributeMaxDynamicSharedMemorySize, GEMM_SMEM);

    LayerParams p1, p2;
    p1.Wq  = (const float*)d_in[3];  p1.bq  = (const float*)d_in[4];
    p1.Wk  = (const float*)d_in[5];  p1.bk  = (const float*)d_in[6];
    p1.Wv  = (const float*)d_in[7];  p1.bv  = (const float*)d_in[8];
    p1.We  = (const float*)d_in[9];
    p1.Wsk = (const float*)d_in[10]; p1.bsk = (const float*)d_in[11];
    p1.Wb  = (const float*)d_in[12];
    p2.Wq  = (const float*)d_in[13]; p2.bq  = (const float*)d_in[14];
    p2.Wk  = (const float*)d_in[15]; p2.bk  = (const float*)d_in[16];
    p2.Wv  = (const float*)d_in[17]; p2.bv  = (const float*)d_in[18];
    p2.We  = (const float*)d_in[19];
    p2.Wsk = (const float*)d_in[20]; p2.bsk = (const float*)d_in[21];
    p2.Wb  = (const float*)d_in[22];

    dim3 ggFull(NPAD / 128, NTOT / 128);
    dim3 ggC0(CHUNK0_BLKS, NTOT / 128);
    dim3 ggC1(CHUNK1_BLKS, NTOT / 128);

    // ---- fork: stream B = conv_w(p2) + CSR build; stream A = conv_x + conv_w(p1) + gemm1
    cudaEventRecord(g_evFork, 0);
    cudaStreamWaitEvent(g_sB, g_evFork, 0);

    conv_w_kernel<<<NTOT, 256, 0, g_sB>>>(p2.Wq, p2.Wk, p2.Wv, p2.Wsk,
                                          p2.bq, p2.bk, p2.bv, p2.bsk, 1);
    zero_cnt_kernel<<<(NN + 255) / 256, 256, 0, g_sB>>>();
    count_deg_kernel<<<(E / 4 + 255) / 256, 256, 0, g_sB>>>(ei, E);
    scan_deg_kernel<<<1, 1024, 0, g_sB>>>(E);
    fill_csr_kernel<<<(E / 4 + 255) / 256, 256, 0, g_sB>>>(ei, ew, E);
    cudaEventRecord(g_evB, g_sB);

    conv_x_kernel<<<(NPAD * DIN) / 1024, 1024>>>(x);
    conv_w_kernel<<<NTOT, 256>>>(p1.Wq, p1.Wk, p1.Wv, p1.Wsk,
                                 p1.bq, p1.bk, p1.bv, p1.bsk, 0);
    gemm_mma_kernel<<<ggFull, 256, GEMM_SMEM>>>(0, 0, 0);   // layer1 -> set0

    cudaStreamWaitEvent(0, g_evB, 0);   // attention needs CSR

    // ---- layer 1 attention (chunked) overlapped with layer 2 GEMM on stream B
    attn_epi_kernel<<<CHUNK0_NODES, 256>>>(p1.We, p1.Wb, 0, nullptr, 0, 0);
    cudaEventRecord(g_evC[0], 0);
    attn_epi_kernel<<<NN - CHUNK0_NODES, 256>>>(p1.We, p1.Wb, 0, nullptr, 0, CHUNK0_NODES);
    cudaEventRecord(g_evC[1], 0);

    cudaStreamWaitEvent(g_sB, g_evC[0], 0);
    gemm_mma_kernel<<<ggC0, 256, GEMM_SMEM, g_sB>>>(1, 1, 0);           // layer2 -> set1
    cudaStreamWaitEvent(g_sB, g_evC[1], 0);
    gemm_mma_kernel<<<ggC1, 256, GEMM_SMEM, g_sB>>>(1, 1, CHUNK0_BLKS);
    cudaEventRecord(g_evG[0], g_sB);

    // ---- layer 2 attention (chunked) overlapped with layer 3 GEMM
    cudaStreamWaitEvent(0, g_evG[0], 0);
    attn_epi_kernel<<<CHUNK0_NODES, 256>>>(p2.We, p2.Wb, 0, nullptr, 1, 0);
    cudaEventRecord(g_evC[2], 0);
    attn_epi_kernel<<<NN - CHUNK0_NODES, 256>>>(p2.We, p2.Wb, 0, nullptr, 1, CHUNK0_NODES);
    cudaEventRecord(g_evC[3], 0);

    cudaStreamWaitEvent(g_sB, g_evC[2], 0);
    gemm_mma_kernel<<<ggC0, 256, GEMM_SMEM, g_sB>>>(1, 0, 0);           // layer3 -> set0
    cudaStreamWaitEvent(g_sB, g_evC[3], 0);
    gemm_mma_kernel<<<ggC1, 256, GEMM_SMEM, g_sB>>>(1, 0, CHUNK0_BLKS);
    cudaEventRecord(g_evG[1], g_sB);

    // ---- layer 3 attention (full) -> d_out
    cudaStreamWaitEvent(0, g_evG[1], 0);
    attn_epi_kernel<<<NN, 256>>>(p2.We, p2.Wb, 1, (float*)d_out, 0, 0);
}

// round 16
// speedup vs baseline: 1.2197x; 1.2197x over previous
#include <cuda_runtime.h>
#include <cuda_bf16.h>
#include <cstdint>
#include <math.h>

#define NN 10000
#define NPAD 10112          // 79 * 128
#define EE 320000
#define DIN 256
#define HEADS 8
#define DH 32
#define HD 256
#define NTOT 1024           // 4 weights x 256 output cols

// ---------------- scratch (static device globals; no allocation) ----------------
__device__ float g_Q[NN * HD];
__device__ float g_K[NN * HD];
__device__ float g_V[NN * HD];
__device__ float g_XR[NN * HD];
__device__ int   g_rowptr[NN + 1];
__device__ int   g_cnt[NN];
__device__ int   g_srcs[EE];
__device__ float g_ews[EE];
// split-bf16 operands for tensor-core GEMM (double-buffered weights)
__device__ __nv_bfloat16 g_Xhi[NPAD * DIN];
__device__ __nv_bfloat16 g_Xlo[NPAD * DIN];
__device__ __nv_bfloat16 g_Wthi0[NTOT * DIN];
__device__ __nv_bfloat16 g_Wtlo0[NTOT * DIN];
__device__ float g_bcat0[NTOT];
__device__ __nv_bfloat16 g_Wthi1[NTOT * DIN];
__device__ __nv_bfloat16 g_Wtlo1[NTOT * DIN];
__device__ float g_bcat1[NTOT];

__device__ __forceinline__ uint32_t smem_u32(const void* p) {
    uint32_t a;
    asm("{ .reg .u64 t; cvta.to.shared.u64 t, %1; cvt.u32.u64 %0, t; }" : "=r"(a) : "l"(p));
    return a;
}

__device__ __forceinline__ void ldm_x4(uint32_t* r, uint32_t addr) {
    asm volatile("ldmatrix.sync.aligned.m8n8.x4.shared.b16 {%0,%1,%2,%3}, [%4];"
                 : "=r"(r[0]), "=r"(r[1]), "=r"(r[2]), "=r"(r[3]) : "r"(addr));
}

__device__ __forceinline__ void mma16816(float* c, const uint32_t* a, const uint32_t* b) {
    asm volatile(
        "mma.sync.aligned.m16n8k16.row.col.f32.bf16.bf16.f32 "
        "{%0,%1,%2,%3}, {%4,%5,%6,%7}, {%8,%9}, {%0,%1,%2,%3};"
        : "+f"(c[0]), "+f"(c[1]), "+f"(c[2]), "+f"(c[3])
        : "r"(a[0]), "r"(a[1]), "r"(a[2]), "r"(a[3]), "r"(b[0]), "r"(b[1]));
}

__device__ __forceinline__ void cp16(uint32_t dst, const void* src) {
    asm volatile("cp.async.cg.shared.global [%0], [%1], 16;" :: "r"(dst), "l"(src));
}
#define CP_COMMIT() asm volatile("cp.async.commit_group;" ::: "memory")
#define CP_WAIT(n)  asm volatile("cp.async.wait_group %0;" :: "n"(n) : "memory")

// ---------------- CSR build ----------------
__global__ void zero_cnt_kernel() {
    int i = blockIdx.x * blockDim.x + threadIdx.x;
    if (i < NN) g_cnt[i] = 0;
}

__global__ void count_deg_kernel(const int* __restrict__ ei, int E) {
    int base = (blockIdx.x * blockDim.x + threadIdx.x) * 4;
#pragma unroll
    for (int i = 0; i < 4; i++) {
        int e = base + i;
        if (e < E) {
            int d = ei[E + e];
            if (d >= 0 && d < NN) atomicAdd(&g_cnt[d], 1);
        }
    }
}

__global__ void scan_deg_kernel(int E) {
    __shared__ int warp_sums[32];
    const int IT = 10;
    int t = threadIdx.x;
    int lane = t & 31, wid = t >> 5;
    int base = t * IT;
    int loc[IT];
    int tot = 0;
#pragma unroll
    for (int i = 0; i < IT; i++) {
        int idx = base + i;
        int v = (idx < NN) ? g_cnt[idx] : 0;
        if (idx < NN) g_cnt[idx] = 0;
        loc[i] = v;
        tot += v;
    }
    int incl = tot;
#pragma unroll
    for (int o = 1; o < 32; o <<= 1) {
        int n = __shfl_up_sync(0xffffffffu, incl, o);
        if (lane >= o) incl += n;
    }
    if (lane == 31) warp_sums[wid] = incl;
    __syncthreads();
    if (wid == 0) {
        int v = warp_sums[lane];
        __syncwarp();
#pragma unroll
        for (int o = 1; o < 32; o <<= 1) {
            int n = __shfl_up_sync(0xffffffffu, v, o);
            if (lane >= o) v += n;
        }
        warp_sums[lane] = v;
    }
    __syncthreads();
    int run = (incl - tot) + (wid > 0 ? warp_sums[wid - 1] : 0);
#pragma unroll
    for (int i = 0; i < IT; i++) {
        int idx = base + i;
        if (idx < NN) g_rowptr[idx] = run;
        run += loc[i];
    }
    if (t == 0) g_rowptr[NN] = E;
}

__global__ void fill_csr_kernel(const int* __restrict__ ei,
                                const float* __restrict__ ew, int E) {
    int base = (blockIdx.x * blockDim.x + threadIdx.x) * 4;
#pragma unroll
    for (int i = 0; i < 4; i++) {
        int e = base + i;
        if (e < E) {
            int d = ei[E + e];
            int s = ei[e];
            if (d >= 0 && d < NN && s >= 0 && s < NN) {
                int pos = atomicAdd(&g_cnt[d], 1);
                int o = g_rowptr[d] + pos;
                if (o >= 0 && o < E) {
                    g_srcs[o] = s;
                    g_ews[o]  = ew[e];
                }
            }
        }
    }
}

// ---------------- conversions: fp32 -> split bf16 ----------------
__global__ __launch_bounds__(1024) void conv_x_kernel(const float* __restrict__ X) {
    int idx = blockIdx.x * blockDim.x + threadIdx.x;
    int row = idx >> 8;
    float v = (row < NN) ? X[idx] : 0.0f;
    __nv_bfloat16 h = __float2bfloat16(v);
    float hv = __bfloat162float(h);
    g_Xhi[idx] = h;
    g_Xlo[idx] = __float2bfloat16(v - hv);
}

__global__ __launch_bounds__(256) void conv_w_kernel(
    const float* __restrict__ W0, const float* __restrict__ W1,
    const float* __restrict__ W2, const float* __restrict__ W3,
    const float* __restrict__ b0, const float* __restrict__ b1,
    const float* __restrict__ b2, const float* __restrict__ b3,
    int dstbuf)
{
    int b = blockIdx.x;
    int w = b >> 8;
    int n = b & 255;
    const float* W; const float* bias;
    switch (w) {
        case 0: W = W0; bias = b0; break;
        case 1: W = W1; bias = b1; break;
        case 2: W = W2; bias = b2; break;
        default: W = W3; bias = b3; break;
    }
    __nv_bfloat16* Whi = dstbuf ? g_Wthi1 : g_Wthi0;
    __nv_bfloat16* Wlo = dstbuf ? g_Wtlo1 : g_Wtlo0;
    float* bc = dstbuf ? g_bcat1 : g_bcat0;
    int k = threadIdx.x;
    float v = W[k * 256 + n];
    __nv_bfloat16 h = __float2bfloat16(v);
    float hv = __bfloat162float(h);
    Whi[b * 256 + k] = h;
    Wlo[b * 256 + k] = __float2bfloat16(v - hv);
    if (k == 0) bc[b] = bias[n];
}

// ---------------- pipelined mma GEMM: [NPAD,256] x [256,1024] -> Q|K|V|XR ----------------
#define KSTR 40
#define STG_ELEMS 20480
#define OFF_AH 0
#define OFF_AL 5120
#define OFF_BH 10240
#define OFF_BL 15360
#define NSTAGE 2
#define GEMM_SMEM (NSTAGE * STG_ELEMS * 2)   // 81920 bytes

__device__ __forceinline__ void gemm_stage(
    __nv_bfloat16* sb, int m0, int n0, int k0, int tid,
    const __nv_bfloat16* __restrict__ Whi, const __nv_bfloat16* __restrict__ Wlo)
{
#pragma unroll
    for (int i = 0; i < 8; i++) {
        int u = tid + i * 256;            // 0..2047, 16B units
        const __nv_bfloat16* src;
        uint32_t doff;
        if (u < 512) {
            int r = u >> 2, c = u & 3;
            src = &g_Xhi[(m0 + r) * 256 + k0 + c * 8];
            doff = OFF_AH + (uint32_t)(r * KSTR + c * 8);
        } else if (u < 1024) {
            int v = u - 512;
            int r = v >> 2, c = v & 3;
            src = &g_Xlo[(m0 + r) * 256 + k0 + c * 8];
            doff = OFF_AL + (uint32_t)(r * KSTR + c * 8);
        } else if (u < 1536) {
            int v = u - 1024;
            int r = v >> 2, c = v & 3;
            src = &Whi[(n0 + r) * 256 + k0 + c * 8];
            doff = OFF_BH + (uint32_t)(r * KSTR + c * 8);
        } else {
            int v = u - 1536;
            int r = v >> 2, c = v & 3;
            src = &Wlo[(n0 + r) * 256 + k0 + c * 8];
            doff = OFF_BL + (uint32_t)(r * KSTR + c * 8);
        }
        cp16(smem_u32(sb + doff), src);
    }
}

__global__ __launch_bounds__(256, 2) void gemm_mma_kernel(int wbuf)
{
    extern __shared__ __nv_bfloat16 dsm[];
    const __nv_bfloat16* Whi = wbuf ? g_Wthi1 : g_Wthi0;
    const __nv_bfloat16* Wlo = wbuf ? g_Wtlo1 : g_Wtlo0;
    const float* bcat = wbuf ? g_bcat1 : g_bcat0;

    int tid = threadIdx.x;
    int lane = tid & 31;
    int warp = tid >> 5;
    int warpM = warp & 3;        // 0..3 (32 rows each)
    int warpN = warp >> 2;       // 0..1 (64 cols each)
    int m0 = blockIdx.x * 128;
    int n0 = blockIdx.y * 128;

    float acc[2][8][4] = {};

    int a_j = lane & 7;
    int a_rowoff = ((lane >> 3) & 1) * 8;
    int a_coloff = (lane >> 4) * 8;
    int b_j = lane & 7;
    int b_rowoff = (lane >> 4) * 8;
    int b_coloff = ((lane >> 3) & 1) * 8;

    gemm_stage(dsm, m0, n0, 0, tid, Whi, Wlo);
    CP_COMMIT();

    for (int kc = 0; kc < 8; kc++) {
        __nv_bfloat16* cur = dsm + (kc & 1) * STG_ELEMS;
        if (kc < 7) {
            gemm_stage(dsm + ((kc + 1) & 1) * STG_ELEMS, m0, n0, (kc + 1) * 32, tid, Whi, Wlo);
            CP_COMMIT();
            CP_WAIT(1);
        } else {
            CP_WAIT(0);
        }
        __syncthreads();

        uint32_t ah_b = smem_u32(cur + OFF_AH);
        uint32_t al_b = smem_u32(cur + OFF_AL);
        uint32_t bh_b = smem_u32(cur + OFF_BH);
        uint32_t bl_b = smem_u32(cur + OFF_BL);

#pragma unroll
        for (int ks = 0; ks < 2; ks++) {
            int kk = ks * 16;
            uint32_t ah[2][4], al[2][4];
#pragma unroll
            for (int mi = 0; mi < 2; mi++) {
                int rbase = warpM * 32 + mi * 16;
                uint32_t off = (uint32_t)((rbase + a_rowoff + a_j) * KSTR + kk + a_coloff) * 2;
                ldm_x4(ah[mi], ah_b + off);
                ldm_x4(al[mi], al_b + off);
            }
#pragma unroll
            for (int half = 0; half < 2; half++) {
                uint32_t bh[4][2], bl[4][2];
#pragma unroll
                for (int bi = 0; bi < 2; bi++) {
                    int nb = warpN * 64 + half * 32 + bi * 16;
                    uint32_t off = (uint32_t)((nb + b_rowoff + b_j) * KSTR + kk + b_coloff) * 2;
                    uint32_t th[4], tl[4];
                    ldm_x4(th, bh_b + off);
                    ldm_x4(tl, bl_b + off);
                    bh[bi * 2][0] = th[0]; bh[bi * 2][1] = th[1];
                    bh[bi * 2 + 1][0] = th[2]; bh[bi * 2 + 1][1] = th[3];
                    bl[bi * 2][0] = tl[0]; bl[bi * 2][1] = tl[1];
                    bl[bi * 2 + 1][0] = tl[2]; bl[bi * 2 + 1][1] = tl[3];
                }
#pragma unroll
                for (int mi = 0; mi < 2; mi++)
#pragma unroll
                    for (int ni = 0; ni < 4; ni++) {
                        float* a4 = acc[mi][half * 4 + ni];
                        mma16816(a4, ah[mi], bh[ni]);
                        mma16816(a4, ah[mi], bl[ni]);
                        mma16816(a4, al[mi], bh[ni]);
                    }
            }
        }
        __syncthreads();
    }

    int wsel = n0 >> 8;
    float* C = (wsel == 0) ? g_Q : (wsel == 1) ? g_K : (wsel == 2) ? g_V : g_XR;
    int cbase = n0 & 255;
#pragma unroll
    for (int mi = 0; mi < 2; mi++) {
        int m = m0 + warpM * 32 + mi * 16 + (lane >> 2);
#pragma unroll
        for (int nj = 0; nj < 8; nj++) {
            int ncol = warpN * 64 + (nj >> 2) * 32 + (nj & 3) * 8 + (lane & 3) * 2;
            int ng = n0 + ncol;
            int col = cbase + ncol;
            float b0v = bcat[ng], b1v = bcat[ng + 1];
            if (m < NN) {
                float2 o = make_float2(acc[mi][nj][0] + b0v, acc[mi][nj][1] + b1v);
                *(float2*)&C[m * HD + col] = o;
            }
            if (m + 8 < NN) {
                float2 o = make_float2(acc[mi][nj][2] + b0v, acc[mi][nj][3] + b1v);
                *(float2*)&C[(m + 8) * HD + col] = o;
            }
        }
    }
}

// ---------------- fused edge attention + beta epilogue (+ split-bf16 emit) ----------------
__global__ __launch_bounds__(256) void attn_epi_kernel(
    const float* __restrict__ We, const float* __restrict__ Wb,
    int last, float* __restrict__ Hext)
{
    __shared__ float hsum[8];
    int node = blockIdx.x;
    int h = threadIdx.x >> 5;
    int lane = threadIdx.x & 31;
    int g = lane >> 3;
    int j = lane & 7;
    int off = h * DH + j * 4;
    int goff = node * HD + off;
    unsigned gmask = 0xFFu << (g * 8);

    float4 q4 = *(const float4*)&g_Q[goff];
    const float sc = 0.17677669529663687f;   // 1/sqrt(32)
    q4.x *= sc; q4.y *= sc; q4.z *= sc; q4.w *= sc;
    float4 we4 = *(const float4*)&We[off];

    float qe = q4.x * we4.x + q4.y * we4.y + q4.z * we4.z + q4.w * we4.w;
    qe += __shfl_xor_sync(gmask, qe, 1);
    qe += __shfl_xor_sync(gmask, qe, 2);
    qe += __shfl_xor_sync(gmask, qe, 4);

    float m = -3.0e38f, s = 0.f, se = 0.f;
    float ax = 0.f, ay = 0.f, az = 0.f, aw = 0.f;
    int beg = g_rowptr[node], end = g_rowptr[node + 1];
    int p = beg + g;
    for (; p + 4 < end; p += 8) {
        int s0 = g_srcs[p];
        int s1 = g_srcs[p + 4];
        float w0 = g_ews[p];
        float w1 = g_ews[p + 4];
        float4 k0 = *(const float4*)&g_K[s0 * HD + off];
        float4 v0 = *(const float4*)&g_V[s0 * HD + off];
        float4 k1 = *(const float4*)&g_K[s1 * HD + off];
        float4 v1 = *(const float4*)&g_V[s1 * HD + off];
        float d0 = q4.x * k0.x + q4.y * k0.y + q4.z * k0.z + q4.w * k0.w;
        float d1 = q4.x * k1.x + q4.y * k1.y + q4.z * k1.z + q4.w * k1.w;
        d0 += __shfl_xor_sync(gmask, d0, 1);
        d1 += __shfl_xor_sync(gmask, d1, 1);
        d0 += __shfl_xor_sync(gmask, d0, 2);
        d1 += __shfl_xor_sync(gmask, d1, 2);
        d0 += __shfl_xor_sync(gmask, d0, 4);
        d1 += __shfl_xor_sync(gmask, d1, 4);
        float al0 = d0 + w0 * qe;
        float al1 = d1 + w1 * qe;
        float nm = fmaxf(m, fmaxf(al0, al1));
        float corr = __expf(m - nm);
        float p0 = __expf(al0 - nm);
        float p1 = __expf(al1 - nm);
        s = s * corr + p0 + p1;
        se = se * corr + p0 * w0 + p1 * w1;
        ax = ax * corr + p0 * v0.x + p1 * v1.x;
        ay = ay * corr + p0 * v0.y + p1 * v1.y;
        az = az * corr + p0 * v0.z + p1 * v1.z;
        aw = aw * corr + p0 * v0.w + p1 * v1.w;
        m = nm;
    }
    for (; p < end; p += 4) {
        int sN = g_srcs[p];
        float w = g_ews[p];
        float4 k4 = *(const float4*)&g_K[sN * HD + off];
        float4 v4 = *(const float4*)&g_V[sN * HD + off];
        float d0 = q4.x * k4.x + q4.y * k4.y + q4.z * k4.z + q4.w * k4.w;
        d0 += __shfl_xor_sync(gmask, d0, 1);
        d0 += __shfl_xor_sync(gmask, d0, 2);
        d0 += __shfl_xor_sync(gmask, d0, 4);
        float alpha = d0 + w * qe;
        float nm = fmaxf(m, alpha);
        float corr = __expf(m - nm);
        float pe = __expf(alpha - nm);
        s = s * corr + pe;
        se = se * corr + pe * w;
        ax = ax * corr + pe * v4.x;
        ay = ay * corr + pe * v4.y;
        az = az * corr + pe * v4.z;
        aw = aw * corr + pe * v4.w;
        m = nm;
    }
#pragma unroll
    for (int o = 8; o <= 16; o <<= 1) {
        float mo = __shfl_xor_sync(0xffffffffu, m, o);
        float so = __shfl_xor_sync(0xffffffffu, s, o);
        float seo = __shfl_xor_sync(0xffffffffu, se, o);
        float bx = __shfl_xor_sync(0xffffffffu, ax, o);
        float by = __shfl_xor_sync(0xffffffffu, ay, o);
        float bz = __shfl_xor_sync(0xffffffffu, az, o);
        float bw = __shfl_xor_sync(0xffffffffu, aw, o);
        float nm = fmaxf(m, mo);
        float c1 = __expf(m - nm);
        float c2 = __expf(mo - nm);
        s = s * c1 + so * c2;
        se = se * c1 + seo * c2;
        ax = ax * c1 + bx * c2;
        ay = ay * c1 + by * c2;
        az = az * c1 + bz * c2;
        aw = aw * c1 + bw * c2;
        m = nm;
    }
    float inv = 1.f / (s + 1e-16f);
    float ox = (ax + se * we4.x) * inv;
    float oy = (ay + se * we4.y) * inv;
    float oz = (az + se * we4.z) * inv;
    float ow = (aw + se * we4.w) * inv;

    float4 xr4 = *(const float4*)&g_XR[goff];
    float4 wb1 = *(const float4*)&Wb[off];
    float4 wb2 = *(const float4*)&Wb[256 + off];
    float4 wb3 = *(const float4*)&Wb[512 + off];
    float part = ox * (wb1.x + wb3.x) + xr4.x * (wb2.x - wb3.x)
               + oy * (wb1.y + wb3.y) + xr4.y * (wb2.y - wb3.y)
               + oz * (wb1.z + wb3.z) + xr4.z * (wb2.z - wb3.z)
               + ow * (wb1.w + wb3.w) + xr4.w * (wb2.w - wb3.w);
    part += __shfl_xor_sync(0xffffffffu, part, 1);
    part += __shfl_xor_sync(0xffffffffu, part, 2);
    part += __shfl_xor_sync(0xffffffffu, part, 4);
    if (lane == 0) hsum[h] = part;
    __syncthreads();
    float dot = hsum[0] + hsum[1] + hsum[2] + hsum[3] +
                hsum[4] + hsum[5] + hsum[6] + hsum[7];
    float beta = 1.f / (1.f + __expf(-dot));
    float4 hv;
    hv.x = beta * xr4.x + (1.f - beta) * ox;
    hv.y = beta * xr4.y + (1.f - beta) * oy;
    hv.z = beta * xr4.z + (1.f - beta) * oz;
    hv.w = beta * xr4.w + (1.f - beta) * ow;

    if (g == 0) {
        if (last) {
            *(float4*)&Hext[goff] = hv;
        } else {
            // emit split bf16 for next layer's GEMM only (fp32 H is never read)
            __nv_bfloat16 h0 = __float2bfloat16(hv.x);
            __nv_bfloat16 h1 = __float2bfloat16(hv.y);
            __nv_bfloat16 h2 = __float2bfloat16(hv.z);
            __nv_bfloat16 h3 = __float2bfloat16(hv.w);
            __nv_bfloat162 hi01; hi01.x = h0; hi01.y = h1;
            __nv_bfloat162 hi23; hi23.x = h2; hi23.y = h3;
            uint2 hiv = make_uint2(*(uint32_t*)&hi01, *(uint32_t*)&hi23);
            *(uint2*)&g_Xhi[goff] = hiv;
            __nv_bfloat162 lo01, lo23;
            lo01.x = __float2bfloat16(hv.x - __bfloat162float(h0));
            lo01.y = __float2bfloat16(hv.y - __bfloat162float(h1));
            lo23.x = __float2bfloat16(hv.z - __bfloat162float(h2));
            lo23.y = __float2bfloat16(hv.w - __bfloat162float(h3));
            uint2 lov = make_uint2(*(uint32_t*)&lo01, *(uint32_t*)&lo23);
            *(uint2*)&g_Xlo[goff] = lov;
        }
    }
}

// ---------------- host side ----------------
struct LayerParams {
    const float *Wq, *bq, *Wk, *bk, *Wv, *bv, *We, *Wsk, *bsk, *Wb;
};

static cudaStream_t g_sB = nullptr;
static cudaEvent_t g_evFork = nullptr, g_evB = nullptr;
namespace {
struct StreamInit {
    StreamInit() {
        cudaStreamCreateWithFlags(&g_sB, cudaStreamNonBlocking);
        cudaEventCreateWithFlags(&g_evFork, cudaEventDisableTiming);
        cudaEventCreateWithFlags(&g_evB, cudaEventDisableTiming);
    }
} g_streamInit;
}

extern "C" void kernel_launch(void* const* d_in, const int* in_sizes, int n_in,
                              void* d_out, int out_size)
{
    const float* x  = (const float*)d_in[0];
    const int*   ei = (const int*)d_in[1];
    const float* ew = (const float*)d_in[2];
    int E = in_sizes[2];

    cudaFuncSetAttribute(gemm_mma_kernel,
                         cudaFuncAttributeMaxDynamicSharedMemorySize, GEMM_SMEM);

    LayerParams p1, p2;
    p1.Wq  = (const float*)d_in[3];  p1.bq  = (const float*)d_in[4];
    p1.Wk  = (const float*)d_in[5];  p1.bk  = (const float*)d_in[6];
    p1.Wv  = (const float*)d_in[7];  p1.bv  = (const float*)d_in[8];
    p1.We  = (const float*)d_in[9];
    p1.Wsk = (const float*)d_in[10]; p1.bsk = (const float*)d_in[11];
    p1.Wb  = (const float*)d_in[12];
    p2.Wq  = (const float*)d_in[13]; p2.bq  = (const float*)d_in[14];
    p2.Wk  = (const float*)d_in[15]; p2.bk  = (const float*)d_in[16];
    p2.Wv  = (const float*)d_in[17]; p2.bv  = (const float*)d_in[18];
    p2.We  = (const float*)d_in[19];
    p2.Wsk = (const float*)d_in[20]; p2.bsk = (const float*)d_in[21];
    p2.Wb  = (const float*)d_in[22];

    dim3 gg(NPAD / 128, NTOT / 128);

    // fork: stream B does conv_w(p2->buf1) + CSR build, hidden under stream A's
    // conv_x + conv_w(p1->buf0) + gemm1.
    cudaEventRecord(g_evFork, 0);
    cudaStreamWaitEvent(g_sB, g_evFork, 0);

    conv_w_kernel<<<NTOT, 256, 0, g_sB>>>(p2.Wq, p2.Wk, p2.Wv, p2.Wsk,
                                          p2.bq, p2.bk, p2.bv, p2.bsk, 1);
    zero_cnt_kernel<<<(NN + 255) / 256, 256, 0, g_sB>>>();
    count_deg_kernel<<<(E / 4 + 255) / 256, 256, 0, g_sB>>>(ei, E);
    scan_deg_kernel<<<1, 1024, 0, g_sB>>>(E);
    fill_csr_kernel<<<(E / 4 + 255) / 256, 256, 0, g_sB>>>(ei, ew, E);
    cudaEventRecord(g_evB, g_sB);

    // stream A (legacy default)
    conv_x_kernel<<<(NPAD * DIN) / 1024, 1024>>>(x);
    conv_w_kernel<<<NTOT, 256>>>(p1.Wq, p1.Wk, p1.Wv, p1.Wsk,
                                 p1.bq, p1.bk, p1.bv, p1.bsk, 0);
    gemm_mma_kernel<<<gg, 256, GEMM_SMEM>>>(0);

    // join: attention needs CSR
    cudaStreamWaitEvent(0, g_evB, 0);

    attn_epi_kernel<<<NN, 256>>>(p1.We, p1.Wb, 0, nullptr);

    gemm_mma_kernel<<<gg, 256, GEMM_SMEM>>>(1);
    attn_epi_kernel<<<NN, 256>>>(p2.We, p2.Wb, 0, nullptr);

    gemm_mma_kernel<<<gg, 256, GEMM_SMEM>>>(1);
    attn_epi_kernel<<<NN, 256>>>(p2.We, p2.Wb, 1, (float*)d_out);
}